// round 3
// baseline (speedup 1.0000x reference)
#include <cuda_runtime.h>
#include <math.h>

// Problem dims (fixed by setup_inputs)
#define BB 4
#define LL 8192
#define DDIM 1024
#define HH 16
#define DH 64
#define MROWS (BB * LL)       // 32768
#define NSPLIT 16

// ---------------- scratch (device globals; no allocs allowed) ----------------
__device__ float g_Qf[MROWS * DDIM];     // phi(x@Wq)
__device__ float g_Kf[MROWS * DDIM];     // phi(x@Wk)
__device__ float g_V [MROWS * DDIM];     // x@Wv
__device__ float g_attn[MROWS * DDIM];   // attention output (head-merged layout)
__device__ float g_kvp[BB * HH * NSPLIT * DH * DH];  // partial Kv
__device__ float g_k1p[BB * HH * NSPLIT * DH];       // partial K1
__device__ float g_kv [BB * HH * DH * DH];
__device__ float g_k1 [BB * HH * DH];

// ---------------- f32x2 helpers (sm_103a packed fp32 pipe) ----------------
__device__ __forceinline__ unsigned long long pk2(float x, float y) {
    unsigned long long r;
    asm("mov.b64 %0, {%1, %2};" : "=l"(r) : "f"(x), "f"(y));
    return r;
}
__device__ __forceinline__ float2 upk2(unsigned long long v) {
    float2 r;
    asm("mov.b64 {%0, %1}, %2;" : "=f"(r.x), "=f"(r.y) : "l"(v));
    return r;
}
__device__ __forceinline__ void fma2(unsigned long long& d,
                                     unsigned long long a,
                                     unsigned long long b) {
    asm("fma.rn.f32x2 %0, %1, %2, %0;" : "+l"(d) : "l"(a), "l"(b));
}

// ---------------- SGEMM: C[M,N] = A[M,K] @ B[K,N], optional phi epilogue ----
// 128x128 block tile, BK=8, 256 threads, 8x8 per thread via f32x2.
template <bool PHI>
__global__ __launch_bounds__(256) void sgemm128(const float* __restrict__ A,
                                                const float* __restrict__ B,
                                                float* __restrict__ C,
                                                int M, int N, int K) {
    __shared__ float As[8][128];   // [k][m] (A tile transposed)
    __shared__ float Bs[8][128];   // [k][n]

    const int t = threadIdx.x;
    const int rowBase = blockIdx.y * 128;
    const int colBase = blockIdx.x * 128;

    // global-load assignments
    const int arow = t >> 1;            // 0..127
    const int acol = (t & 1) * 4;       // 0 or 4
    const int brow = t >> 5;            // 0..7
    const int bcol = (t & 31) * 4;      // 0..124

    // compute-tile assignment: warps 4(m) x 2(n); lanes 4(m) x 8(n)
    const int warp = t >> 5, lane = t & 31;
    const int rowOff = (warp >> 1) * 32 + (lane >> 3) * 8;   // 0..120
    const int colOff = (warp & 1) * 64 + (lane & 7) * 8;     // 0..120

    unsigned long long acc[8][4];
#pragma unroll
    for (int i = 0; i < 8; i++)
#pragma unroll
        for (int j = 0; j < 4; j++) acc[i][j] = 0ull;

    const float* Aptr = A + (rowBase + arow) * K + acol;
    const float* Bptr = B + brow * N + colBase + bcol;

    float4 aReg = *(const float4*)Aptr;
    float4 bReg = *(const float4*)Bptr;

    for (int k0 = 0; k0 < K; k0 += 8) {
        // commit prefetched tile to smem
        As[acol + 0][arow] = aReg.x;
        As[acol + 1][arow] = aReg.y;
        As[acol + 2][arow] = aReg.z;
        As[acol + 3][arow] = aReg.w;
        *(float4*)&Bs[brow][bcol] = bReg;
        __syncthreads();

        if (k0 + 8 < K) {
            aReg = *(const float4*)(Aptr + k0 + 8);
            bReg = *(const float4*)(Bptr + (size_t)(k0 + 8) * N);
        }

#pragma unroll
        for (int kk = 0; kk < 8; kk++) {
            float4 a0 = *(const float4*)&As[kk][rowOff];
            float4 a1 = *(const float4*)&As[kk][rowOff + 4];
            float4 b0 = *(const float4*)&Bs[kk][colOff];
            float4 b1 = *(const float4*)&Bs[kk][colOff + 4];
            unsigned long long bb[4] = {pk2(b0.x, b0.y), pk2(b0.z, b0.w),
                                        pk2(b1.x, b1.y), pk2(b1.z, b1.w)};
            float av[8] = {a0.x, a0.y, a0.z, a0.w, a1.x, a1.y, a1.z, a1.w};
#pragma unroll
            for (int i = 0; i < 8; i++) {
                unsigned long long aa = pk2(av[i], av[i]);
#pragma unroll
                for (int j = 0; j < 4; j++) fma2(acc[i][j], aa, bb[j]);
            }
        }
        __syncthreads();
    }

    // epilogue
#pragma unroll
    for (int i = 0; i < 8; i++) {
        float o[8];
#pragma unroll
        for (int j = 0; j < 4; j++) {
            float2 v = upk2(acc[i][j]);
            o[2 * j] = v.x;
            o[2 * j + 1] = v.y;
        }
        if (PHI) {
#pragma unroll
            for (int e = 0; e < 8; e++)
                o[e] = (o[e] > 0.f) ? (o[e] + 1.f) : expf(o[e]);  // elu+1
        }
        float* Cr = C + (size_t)(rowBase + rowOff + i) * N + colBase + colOff;
        *(float4*)Cr = make_float4(o[0], o[1], o[2], o[3]);
        *(float4*)(Cr + 4) = make_float4(o[4], o[5], o[6], o[7]);
    }
}

// ---------------- Kv / K1 partial reduction over L-chunks ----------------
// grid (NSPLIT, B*H), 256 threads. Deterministic: fixed split + fixed-order sum.
__global__ __launch_bounds__(256) void kv_partial() {
    const int s = blockIdx.x;          // 0..NSPLIT-1
    const int bh = blockIdx.y;         // 0..63
    const int b = bh >> 4;
    const int h = bh & 15;
    const int Lc = LL / NSPLIT;        // 512
    const int rowbase = b * LL + s * Lc;
    const int coff = h * DH;

    __shared__ float Ks[8][64];
    __shared__ float Vs[8][64];

    const int t = threadIdx.x;
    const int m0 = (t >> 4) * 4;       // 0..60
    const int n0 = (t & 15) * 4;       // 0..60
    const int lr = t >> 5;             // 0..7
    const int lc = (t & 31) * 2;       // 0..62

    float acc[4][4];
#pragma unroll
    for (int i = 0; i < 4; i++)
#pragma unroll
        for (int j = 0; j < 4; j++) acc[i][j] = 0.f;
    float k1 = 0.f;

    for (int l0 = 0; l0 < Lc; l0 += 8) {
        __syncthreads();
        const size_t roff = (size_t)(rowbase + l0 + lr) * DDIM + coff + lc;
        *(float2*)&Ks[lr][lc] = *(const float2*)&g_Kf[roff];
        *(float2*)&Vs[lr][lc] = *(const float2*)&g_V[roff];
        __syncthreads();
#pragma unroll
        for (int r = 0; r < 8; r++) {
            float4 kf = *(const float4*)&Ks[r][m0];
            float4 vf = *(const float4*)&Vs[r][n0];
            float km[4] = {kf.x, kf.y, kf.z, kf.w};
            float vn[4] = {vf.x, vf.y, vf.z, vf.w};
#pragma unroll
            for (int i = 0; i < 4; i++)
#pragma unroll
                for (int j = 0; j < 4; j++) acc[i][j] += km[i] * vn[j];
        }
        if (t < 64) {
#pragma unroll
            for (int r = 0; r < 8; r++) k1 += Ks[r][t];
        }
    }

    float* outp = &g_kvp[((size_t)bh * NSPLIT + s) * (DH * DH)];
#pragma unroll
    for (int i = 0; i < 4; i++)
#pragma unroll
        for (int j = 0; j < 4; j++) outp[(m0 + i) * DH + n0 + j] = acc[i][j];
    if (t < 64) g_k1p[(bh * NSPLIT + s) * DH + t] = k1;
}

__global__ __launch_bounds__(256) void kv_reduce() {
    const int bh = blockIdx.x;
    const int t = threadIdx.x;
#pragma unroll
    for (int i = 0; i < 16; i++) {
        const int idx = t * 16 + i;
        float sum = 0.f;
#pragma unroll
        for (int s = 0; s < NSPLIT; s++)
            sum += g_kvp[((size_t)bh * NSPLIT + s) * (DH * DH) + idx];
        g_kv[bh * (DH * DH) + idx] = sum;
    }
    if (t < 64) {
        float sum = 0.f;
#pragma unroll
        for (int s = 0; s < NSPLIT; s++)
            sum += g_k1p[(bh * NSPLIT + s) * DH + t];
        g_k1[bh * DH + t] = sum;
    }
}

// ---------------- apply: out = (Qf @ Kv) / (Qf @ K1 + eps) ----------------
// grid (L/128, B*H), 256 threads. Kv head (16 KB) cached in smem.
__global__ __launch_bounds__(256) void apply_attn() {
    const int bh = blockIdx.y;
    const int b = bh >> 4;
    const int h = bh & 15;
    const int l0 = b * LL + blockIdx.x * 128;
    const int coff = h * DH;

    __shared__ float KvS[DH * DH];
    __shared__ float K1S[DH];
    __shared__ float Qs[16][64];
    __shared__ float dpart[16][4];
    __shared__ float rinv[16];

    const int t = threadIdx.x;
    for (int i = t; i < DH * DH; i += 256) KvS[i] = g_kv[bh * (DH * DH) + i];
    if (t < 64) K1S[t] = g_k1[bh * DH + t];
    __syncthreads();

    const int n = t & 63;
    const int rg = t >> 6;  // 0..3 -> rows rg*4 .. rg*4+3 of the 16-row tile

    for (int r0 = 0; r0 < 128; r0 += 16) {
        {
            const int r = t >> 4, c = (t & 15) * 4;
            *(float4*)&Qs[r][c] =
                *(const float4*)&g_Qf[(size_t)(l0 + r0 + r) * DDIM + coff + c];
        }
        __syncthreads();

        if (t < 64) {
            const int r = t >> 2, seg = (t & 3) * 16;
            float d = 0.f;
#pragma unroll
            for (int m = 0; m < 16; m++) d += Qs[r][seg + m] * K1S[seg + m];
            dpart[r][t & 3] = d;
        }
        __syncthreads();
        if (t < 16) {
            rinv[t] = 1.f / (dpart[t][0] + dpart[t][1] + dpart[t][2] +
                             dpart[t][3] + 1e-6f);
        }
        __syncthreads();

        float a0 = 0.f, a1 = 0.f, a2 = 0.f, a3 = 0.f;
#pragma unroll 8
        for (int m = 0; m < 64; m++) {
            const float kv = KvS[m * 64 + n];
            a0 += Qs[rg * 4 + 0][m] * kv;
            a1 += Qs[rg * 4 + 1][m] * kv;
            a2 += Qs[rg * 4 + 2][m] * kv;
            a3 += Qs[rg * 4 + 3][m] * kv;
        }
        const size_t base = (size_t)(l0 + r0 + rg * 4) * DDIM + coff + n;
        g_attn[base + 0 * DDIM] = a0 * rinv[rg * 4 + 0];
        g_attn[base + 1 * DDIM] = a1 * rinv[rg * 4 + 1];
        g_attn[base + 2 * DDIM] = a2 * rinv[rg * 4 + 2];
        g_attn[base + 3 * DDIM] = a3 * rinv[rg * 4 + 3];
        __syncthreads();
    }
}

// ---------------- launch ----------------
extern "C" void kernel_launch(void* const* d_in, const int* in_sizes, int n_in,
                              void* d_out, int out_size) {
    (void)in_sizes; (void)n_in; (void)out_size;
    const float* x  = (const float*)d_in[0];
    const float* Wq = (const float*)d_in[1];
    const float* Wk = (const float*)d_in[2];
    const float* Wv = (const float*)d_in[3];
    const float* Wo = (const float*)d_in[4];
    float* out = (float*)d_out;

    float *Qf, *Kf, *V, *attn;
    cudaGetSymbolAddress((void**)&Qf, g_Qf);
    cudaGetSymbolAddress((void**)&Kf, g_Kf);
    cudaGetSymbolAddress((void**)&V,  g_V);
    cudaGetSymbolAddress((void**)&attn, g_attn);

    const dim3 gg(DDIM / 128, MROWS / 128);  // (8, 256)

    sgemm128<true ><<<gg, 256>>>(x, Wq, Qf, MROWS, DDIM, DDIM);  // Qf = phi(xWq)
    sgemm128<true ><<<gg, 256>>>(x, Wk, Kf, MROWS, DDIM, DDIM);  // Kf = phi(xWk)
    sgemm128<false><<<gg, 256>>>(x, Wv, V,  MROWS, DDIM, DDIM);  // V  = xWv

    kv_partial<<<dim3(NSPLIT, BB * HH), 256>>>();
    kv_reduce<<<BB * HH, 256>>>();
    apply_attn<<<dim3(LL / 128, BB * HH), 256>>>();

    sgemm128<false><<<gg, 256>>>(attn, Wo, out, MROWS, DDIM, DDIM);
}

// round 6
// speedup vs baseline: 3.0595x; 3.0595x over previous
#include <cuda_runtime.h>
#include <math.h>
#include <stdint.h>

// Problem dims (fixed by setup_inputs)
#define BB 4
#define LL 8192
#define DDIM 1024
#define HH 16
#define DH 64
#define MROWS (BB * LL)       // 32768
#define NSPLIT 64

// ---------------- scratch (device globals; no allocs allowed) ----------------
__device__ float g_Qf[(size_t)MROWS * DDIM];   // phi(x@Wq) fp32
__device__ float g_Kf[(size_t)MROWS * DDIM];   // phi(x@Wk) fp32
__device__ float g_V [(size_t)MROWS * DDIM];   // x@Wv fp32
__device__ float g_xt[(size_t)MROWS * DDIM];   // x rounded to tf32
__device__ float g_at[(size_t)MROWS * DDIM];   // attn out, tf32-rounded
__device__ float g_Wt[(size_t)4 * DDIM * DDIM];// 4 weights tf32-rounded
__device__ float g_kvp[(size_t)BB * HH * NSPLIT * DH * DH];
__device__ float g_k1p[(size_t)BB * HH * NSPLIT * DH];
__device__ float g_kv [(size_t)BB * HH * DH * DH];
__device__ float g_k1 [(size_t)BB * HH * DH];

// ---------------- PTX helpers ----------------
__device__ __forceinline__ uint32_t s2u(const void* p) {
    uint32_t a;
    asm("{ .reg .u64 t; cvta.to.shared.u64 t, %1; cvt.u32.u64 %0, t; }"
        : "=r"(a) : "l"(p));
    return a;
}
__device__ __forceinline__ void cpasync16(uint32_t dst, const void* src) {
    asm volatile("cp.async.ca.shared.global [%0], [%1], 16;"
                 :: "r"(dst), "l"(src) : "memory");
}
__device__ __forceinline__ void cpcommit() {
    asm volatile("cp.async.commit_group;" ::: "memory");
}
template <int N>
__device__ __forceinline__ void cpwait() {
    asm volatile("cp.async.wait_group %0;" :: "n"(N) : "memory");
}
__device__ __forceinline__ uint32_t f2tf32(float v) {
    uint32_t o;
    asm("cvt.rna.tf32.f32 %0, %1;" : "=r"(o) : "f"(v));
    return o;
}
// D(16x8) += A(16x8, tf32) * B(8x8, tf32), fp32 accumulate
__device__ __forceinline__ void mma8(float* d, const uint32_t* a,
                                     uint32_t b0, uint32_t b1) {
    asm volatile(
        "mma.sync.aligned.m16n8k8.row.col.f32.tf32.tf32.f32 "
        "{%0,%1,%2,%3}, {%4,%5,%6,%7}, {%8,%9}, {%0,%1,%2,%3};"
        : "+f"(d[0]), "+f"(d[1]), "+f"(d[2]), "+f"(d[3])
        : "r"(a[0]), "r"(a[1]), "r"(a[2]), "r"(a[3]), "r"(b0), "r"(b1));
}

// ---------------- tf32 tensor-core GEMM ----------------
// C[M,1024] = A[M,1024] @ W[1024,1024]  (A, W pre-rounded to tf32)
// CTA 128x256, 8 warps (2m x 4n), warp tile 64x64, BK=32, 3-stage cp.async.
#define BM 128
#define BN 256
#define BKC 32
#define NCH (DDIM / BKC)          // 32
#define APAD 36                   // floats per A smem row (144B, 16B-aligned)
#define BPAD 264                  // floats per B smem row (1056B, 16B-aligned)
#define A_ST (BM * APAD)          // 4608 floats
#define B_ST (BKC * BPAD)         // 8448 floats
#define STG (A_ST + B_ST)         // 13056 floats = 52224 B
#define GEMM_SMEM (3 * STG * 4)   // 156672 B

__device__ __forceinline__ void load_chunk(int c, uint32_t smb,
                                           const float* __restrict__ A,
                                           const float* __restrict__ B,
                                           int mBase, int nBase, int tid) {
    if (c >= NCH) return;
    const uint32_t stg = smb + (uint32_t)(c % 3) * (STG * 4);
    const float* Ab = A + (size_t)mBase * DDIM + c * BKC;
#pragma unroll
    for (int i = 0; i < 4; i++) {
        const int v = tid + i * 256;
        const int r = v >> 3, cc = v & 7;
        cpasync16(stg + r * (APAD * 4) + cc * 16, Ab + (size_t)r * DDIM + cc * 4);
    }
    const uint32_t stgB = stg + A_ST * 4;
    const float* Bb = B + (size_t)c * BKC * DDIM + nBase;
#pragma unroll
    for (int i = 0; i < 8; i++) {
        const int v = tid + i * 256;
        const int r = v >> 6, cc = v & 63;
        cpasync16(stgB + r * (BPAD * 4) + cc * 16, Bb + (size_t)r * DDIM + cc * 4);
    }
    cpcommit();
}

template <bool PHI>
__global__ __launch_bounds__(256, 1) void gemm_tf32(
    const float* __restrict__ A, const float* __restrict__ B,
    float* __restrict__ C) {
    extern __shared__ __align__(16) float sm[];
    const uint32_t smb = s2u(sm);
    const int tid = threadIdx.x;
    const int lane = tid & 31, warp = tid >> 5;
    const int g = lane >> 2, tg = lane & 3;
    const int wm = warp & 1, wn = warp >> 1;        // 2 x 4 warp grid
    const int mBase = blockIdx.y * BM;
    const int nBase = blockIdx.x * BN;

    float acc[4][8][4];
#pragma unroll
    for (int i = 0; i < 4; i++)
#pragma unroll
        for (int j = 0; j < 8; j++)
#pragma unroll
            for (int q = 0; q < 4; q++) acc[i][j][q] = 0.f;

    load_chunk(0, smb, A, B, mBase, nBase, tid);
    load_chunk(1, smb, A, B, mBase, nBase, tid);

    for (int c = 0; c < NCH; c++) {
        if (c + 1 < NCH) cpwait<1>(); else cpwait<0>();
        __syncthreads();
        load_chunk(c + 2, smb, A, B, mBase, nBase, tid);

        const uint32_t* As = (const uint32_t*)(sm + (c % 3) * STG);
        const uint32_t* Bs = As + A_ST;
#pragma unroll
        for (int ks = 0; ks < 4; ks++) {
            const int k0 = ks * 8;
            uint32_t a[4][4];
#pragma unroll
            for (int i = 0; i < 4; i++) {
                const int m0 = wm * 64 + i * 16;
                a[i][0] = As[(m0 + g) * APAD + k0 + tg];
                a[i][1] = As[(m0 + g + 8) * APAD + k0 + tg];
                a[i][2] = As[(m0 + g) * APAD + k0 + tg + 4];
                a[i][3] = As[(m0 + g + 8) * APAD + k0 + tg + 4];
            }
#pragma unroll
            for (int j = 0; j < 8; j++) {
                const int n0 = wn * 64 + j * 8;
                const uint32_t b0 = Bs[(k0 + tg) * BPAD + n0 + g];
                const uint32_t b1 = Bs[(k0 + tg + 4) * BPAD + n0 + g];
#pragma unroll
                for (int i = 0; i < 4; i++) mma8(acc[i][j], a[i], b0, b1);
            }
        }
    }

    // epilogue: c0,c1 -> (row g, cols 2tg,2tg+1); c2,c3 -> row g+8
#pragma unroll
    for (int i = 0; i < 4; i++) {
        const int mr = mBase + wm * 64 + i * 16 + g;
#pragma unroll
        for (int j = 0; j < 8; j++) {
            const int nc = nBase + wn * 64 + j * 8 + 2 * tg;
            float v0 = acc[i][j][0], v1 = acc[i][j][1];
            float v2 = acc[i][j][2], v3 = acc[i][j][3];
            if (PHI) {
                v0 = (v0 > 0.f) ? (v0 + 1.f) : expf(v0);
                v1 = (v1 > 0.f) ? (v1 + 1.f) : expf(v1);
                v2 = (v2 > 0.f) ? (v2 + 1.f) : expf(v2);
                v3 = (v3 > 0.f) ? (v3 + 1.f) : expf(v3);
            }
            *(float2*)(C + (size_t)mr * DDIM + nc) = make_float2(v0, v1);
            *(float2*)(C + (size_t)(mr + 8) * DDIM + nc) = make_float2(v2, v3);
        }
    }
}

// ---------------- fp32 -> tf32-rounded fp32 ----------------
__global__ __launch_bounds__(256) void to_tf32(const float* __restrict__ in,
                                               float* __restrict__ out) {
    const size_t i = ((size_t)blockIdx.x * 256 + threadIdx.x) * 4;
    const float4 a = *(const float4*)(in + i);
    uint4 o;
    o.x = f2tf32(a.x); o.y = f2tf32(a.y); o.z = f2tf32(a.z); o.w = f2tf32(a.w);
    *(uint4*)(out + i) = o;
}

// ---------------- Kv / K1 partial reduction over L-chunks ----------------
__global__ __launch_bounds__(256) void kv_partial() {
    const int s = blockIdx.x;          // 0..NSPLIT-1
    const int bh = blockIdx.y;         // 0..63
    const int b = bh >> 4;
    const int h = bh & 15;
    const int Lc = LL / NSPLIT;        // 128
    const int rowbase = b * LL + s * Lc;
    const int coff = h * DH;

    __shared__ float Ks[8][64];
    __shared__ float Vs[8][64];

    const int t = threadIdx.x;
    const int m0 = (t >> 4) * 4;
    const int n0 = (t & 15) * 4;
    const int lr = t >> 5;
    const int lc = (t & 31) * 2;

    float acc[4][4];
#pragma unroll
    for (int i = 0; i < 4; i++)
#pragma unroll
        for (int j = 0; j < 4; j++) acc[i][j] = 0.f;
    float k1 = 0.f;

    for (int l0 = 0; l0 < Lc; l0 += 8) {
        __syncthreads();
        const size_t roff = (size_t)(rowbase + l0 + lr) * DDIM + coff + lc;
        *(float2*)&Ks[lr][lc] = *(const float2*)&g_Kf[roff];
        *(float2*)&Vs[lr][lc] = *(const float2*)&g_V[roff];
        __syncthreads();
#pragma unroll
        for (int r = 0; r < 8; r++) {
            float4 kf = *(const float4*)&Ks[r][m0];
            float4 vf = *(const float4*)&Vs[r][n0];
            float km[4] = {kf.x, kf.y, kf.z, kf.w};
            float vn[4] = {vf.x, vf.y, vf.z, vf.w};
#pragma unroll
            for (int i = 0; i < 4; i++)
#pragma unroll
                for (int j = 0; j < 4; j++) acc[i][j] += km[i] * vn[j];
        }
        if (t < 64) {
#pragma unroll
            for (int r = 0; r < 8; r++) k1 += Ks[r][t];
        }
    }

    float* outp = &g_kvp[((size_t)bh * NSPLIT + s) * (DH * DH)];
#pragma unroll
    for (int i = 0; i < 4; i++)
#pragma unroll
        for (int j = 0; j < 4; j++) outp[(m0 + i) * DH + n0 + j] = acc[i][j];
    if (t < 64) g_k1p[((size_t)bh * NSPLIT + s) * DH + t] = k1;
}

__global__ __launch_bounds__(256) void kv_reduce() {
    const int bh = blockIdx.x;
    const int t = threadIdx.x;
#pragma unroll
    for (int i = 0; i < 16; i++) {
        const int idx = t * 16 + i;
        float sum = 0.f;
        for (int s = 0; s < NSPLIT; s++)
            sum += g_kvp[((size_t)bh * NSPLIT + s) * (DH * DH) + idx];
        g_kv[(size_t)bh * (DH * DH) + idx] = sum;
    }
    if (t < 64) {
        float sum = 0.f;
        for (int s = 0; s < NSPLIT; s++)
            sum += g_k1p[((size_t)bh * NSPLIT + s) * DH + t];
        g_k1[bh * DH + t] = sum;
    }
}

// ---- apply: attn = (Qf @ Kv) / (Qf @ K1 + eps), tf32-rounded fp32 out ----
__global__ __launch_bounds__(256) void apply_attn() {
    const int bh = blockIdx.y;
    const int b = bh >> 4;
    const int h = bh & 15;
    const int l0 = b * LL + blockIdx.x * 128;
    const int coff = h * DH;

    __shared__ float KvS[DH * DH];
    __shared__ float K1S[DH];
    __shared__ float Qs[16][64];
    __shared__ float dpart[16][4];
    __shared__ float rinv[16];

    const int t = threadIdx.x;
    for (int i = t; i < DH * DH; i += 256) KvS[i] = g_kv[(size_t)bh * (DH * DH) + i];
    if (t < 64) K1S[t] = g_k1[bh * DH + t];
    __syncthreads();

    const int n = t & 63;
    const int rg = t >> 6;

    for (int r0 = 0; r0 < 128; r0 += 16) {
        {
            const int r = t >> 4, c = (t & 15) * 4;
            *(float4*)&Qs[r][c] =
                *(const float4*)&g_Qf[(size_t)(l0 + r0 + r) * DDIM + coff + c];
        }
        __syncthreads();

        if (t < 64) {
            const int r = t >> 2, seg = (t & 3) * 16;
            float d = 0.f;
#pragma unroll
            for (int m = 0; m < 16; m++) d += Qs[r][seg + m] * K1S[seg + m];
            dpart[r][t & 3] = d;
        }
        __syncthreads();
        if (t < 16) {
            rinv[t] = 1.f / (dpart[t][0] + dpart[t][1] + dpart[t][2] +
                             dpart[t][3] + 1e-6f);
        }
        __syncthreads();

        float a0 = 0.f, a1 = 0.f, a2 = 0.f, a3 = 0.f;
#pragma unroll 8
        for (int m = 0; m < 64; m++) {
            const float kv = KvS[m * 64 + n];
            a0 += Qs[rg * 4 + 0][m] * kv;
            a1 += Qs[rg * 4 + 1][m] * kv;
            a2 += Qs[rg * 4 + 2][m] * kv;
            a3 += Qs[rg * 4 + 3][m] * kv;
        }
        const size_t base = (size_t)(l0 + r0 + rg * 4) * DDIM + coff + n;
        const float vv[4] = {a0 * rinv[rg * 4 + 0], a1 * rinv[rg * 4 + 1],
                             a2 * rinv[rg * 4 + 2], a3 * rinv[rg * 4 + 3]};
#pragma unroll
        for (int q = 0; q < 4; q++)
            g_at[base + (size_t)q * DDIM] = __uint_as_float(f2tf32(vv[q]));
        __syncthreads();
    }
}

// ---------------- launch ----------------
extern "C" void kernel_launch(void* const* d_in, const int* in_sizes, int n_in,
                              void* d_out, int out_size) {
    (void)in_sizes; (void)n_in; (void)out_size;
    const float* x  = (const float*)d_in[0];
    const float* Wq = (const float*)d_in[1];
    const float* Wk = (const float*)d_in[2];
    const float* Wv = (const float*)d_in[3];
    const float* Wo = (const float*)d_in[4];
    float* out = (float*)d_out;

    float *Qf, *Kf, *V, *xt, *at, *Wt;
    cudaGetSymbolAddress((void**)&Qf, g_Qf);
    cudaGetSymbolAddress((void**)&Kf, g_Kf);
    cudaGetSymbolAddress((void**)&V,  g_V);
    cudaGetSymbolAddress((void**)&xt, g_xt);
    cudaGetSymbolAddress((void**)&at, g_at);
    cudaGetSymbolAddress((void**)&Wt, g_Wt);

    cudaFuncSetAttribute(gemm_tf32<true>,
                         cudaFuncAttributeMaxDynamicSharedMemorySize, GEMM_SMEM);
    cudaFuncSetAttribute(gemm_tf32<false>,
                         cudaFuncAttributeMaxDynamicSharedMemorySize, GEMM_SMEM);

    const size_t WSZ = (size_t)DDIM * DDIM;               // 1M floats
    const int wblocks = (int)(WSZ / (256 * 4));           // 1024
    to_tf32<<<wblocks, 256>>>(Wq, Wt + 0 * WSZ);
    to_tf32<<<wblocks, 256>>>(Wk, Wt + 1 * WSZ);
    to_tf32<<<wblocks, 256>>>(Wv, Wt + 2 * WSZ);
    to_tf32<<<wblocks, 256>>>(Wo, Wt + 3 * WSZ);
    to_tf32<<<(int)(((size_t)MROWS * DDIM) / (256 * 4)), 256>>>(x, xt);

    const dim3 gg(DDIM / BN, MROWS / BM);                 // (4, 256)
    gemm_tf32<true ><<<gg, 256, GEMM_SMEM>>>(xt, Wt + 0 * WSZ, Qf);
    gemm_tf32<true ><<<gg, 256, GEMM_SMEM>>>(xt, Wt + 1 * WSZ, Kf);
    gemm_tf32<false><<<gg, 256, GEMM_SMEM>>>(xt, Wt + 2 * WSZ, V);

    kv_partial<<<dim3(NSPLIT, BB * HH), 256>>>();
    kv_reduce<<<BB * HH, 256>>>();
    apply_attn<<<dim3(LL / 128, BB * HH), 256>>>();

    gemm_tf32<false><<<gg, 256, GEMM_SMEM>>>(at, Wt + 3 * WSZ, out);
}